// round 16
// baseline (speedup 1.0000x reference)
#include <cuda_runtime.h>

#define BB 64
#define TT 577
#define DD 768
#define DENS 519      // int(577*0.9)
#define NSKIP 58      // 577 - 519
#define D4 (DD/4)     // 192 float4 per row
#define RPB 8         // source rows per scatter block
#define NROWS (BB*TT) // 36928
#define NSCAT (NROWS/RPB) // 4616
#define NT 192

// Scratch (no device allocation allowed)
__device__ float g_logits[NROWS];

// ---------------- Kernel 1: logits = x @ w + b  (one warp per TWO rows) ----------------
// Verified ~21us @ ~70% DRAM — unchanged.
__global__ void logits_kernel(const float* __restrict__ x,
                              const float* __restrict__ w,
                              const float* __restrict__ bias) {
    int warpsPerBlock = blockDim.x >> 5;
    int warpId = threadIdx.x >> 5;
    int lane   = threadIdx.x & 31;
    int pair = blockIdx.x * warpsPerBlock + warpId;
    int row0 = pair * 2;
    if (row0 >= NROWS) return;

    const float4* xr0 = reinterpret_cast<const float4*>(x) + (size_t)row0 * D4;
    const float4* xr1 = xr0 + D4;
    const float4* w4  = reinterpret_cast<const float4*>(w);

    float4 a0[6], a1[6], wv[6];
    #pragma unroll
    for (int k = 0; k < 6; k++) a0[k] = xr0[k*32 + lane];
    #pragma unroll
    for (int k = 0; k < 6; k++) a1[k] = xr1[k*32 + lane];
    #pragma unroll
    for (int k = 0; k < 6; k++) wv[k] = __ldg(&w4[k*32 + lane]);

    float acc0 = 0.f, acc1 = 0.f;
    #pragma unroll
    for (int k = 0; k < 6; k++) {
        acc0 = fmaf(a0[k].x, wv[k].x, acc0);
        acc0 = fmaf(a0[k].y, wv[k].y, acc0);
        acc0 = fmaf(a0[k].z, wv[k].z, acc0);
        acc0 = fmaf(a0[k].w, wv[k].w, acc0);
        acc1 = fmaf(a1[k].x, wv[k].x, acc1);
        acc1 = fmaf(a1[k].y, wv[k].y, acc1);
        acc1 = fmaf(a1[k].z, wv[k].z, acc1);
        acc1 = fmaf(a1[k].w, wv[k].w, acc1);
    }
    #pragma unroll
    for (int off = 16; off; off >>= 1) {
        acc0 += __shfl_xor_sync(0xffffffffu, acc0, off);
        acc1 += __shfl_xor_sync(0xffffffffu, acc1, off);
    }
    if (lane == 0) {
        float bv = bias[0];
        g_logits[row0]     = acc0 + bv;
        g_logits[row0 + 1] = acc1 + bv;
    }
}

// ---------------- Kernel 2: scatter + summary, block-local cooperative rank ----------------
// Blocks [0, BB)        : rank whole batch (broadcast loop, 4 rows/thread) + softmax + summary
// Blocks [BB, BB+NSCAT) : front-issue 8 x loads; 192-thread cooperative count -> 8 ranks; store
__global__ void __launch_bounds__(NT)
move_kernel(const float* __restrict__ x, float* __restrict__ out) {
    const float4* xin = reinterpret_cast<const float4*>(x);
    float4* o4 = reinterpret_cast<float4*>(out);
    const unsigned skipBase = (unsigned)(BB * DENS) * D4;   // float4 units, < 2^31
    const unsigned sumBase  = (unsigned)(BB * (DENS + NSKIP)) * D4;
    int tid  = threadIdx.x;
    int wrp  = tid >> 5;        // 0..5
    int lane = tid & 31;

    if (blockIdx.x < BB) {
        // ======== summary block for batch b ========
        __shared__ float s[TT];
        __shared__ float skipP[NSKIP];
        __shared__ float skipE[NSKIP];
        __shared__ int   sidx[64];      // padded
        __shared__ float swgt[64];      // padded
        int b = blockIdx.x;

        for (int i = tid; i < TT; i += NT) s[i] = g_logits[b*TT + i];
        if (tid < 64) { sidx[tid] = 0; swgt[tid] = 0.f; }
        if (tid < NSKIP) skipP[tid] = 0.f;
        __syncthreads();

        // each thread ranks rows tid, tid+192, tid+384, tid+576 (4 slices cover 577)
        float my0 = (tid        < TT) ? s[tid]        : 0.f;
        float my1 = (tid + NT   < TT) ? s[tid + NT]   : 0.f;
        float my2 = (tid + 2*NT < TT) ? s[tid + 2*NT] : 0.f;
        float my3 = (tid + 3*NT < TT) ? s[tid + 3*NT] : 0.f;   // only tid==0: row 576
        int c0 = 0, c1 = 0, c2 = 0, c3 = 0;
        for (int j = 0; j < TT; j++) {
            float vj = s[j];            // broadcast: conflict-free
            c0 += (vj > my0) || (vj == my0 && j < tid);
            c1 += (vj > my1) || (vj == my1 && j < tid + NT);
            c2 += (vj > my2) || (vj == my2 && j < tid + 2*NT);
            c3 += (vj > my3) || (vj == my3 && j < tid + 3*NT);
        }
        // record skipped rows (rank >= DENS)
        if (tid < TT && c0 >= DENS) {
            int pos = (TT-1) - c0; sidx[pos] = tid;
            skipP[pos] = 1.f / (1.f + expf(-my0));
        }
        if (tid + NT < TT && c1 >= DENS) {
            int pos = (TT-1) - c1; sidx[pos] = tid + NT;
            skipP[pos] = 1.f / (1.f + expf(-my1));
        }
        if (tid + 2*NT < TT && c2 >= DENS) {
            int pos = (TT-1) - c2; sidx[pos] = tid + 2*NT;
            skipP[pos] = 1.f / (1.f + expf(-my2));
        }
        if (tid + 3*NT < TT && c3 >= DENS) {
            int pos = (TT-1) - c3; sidx[pos] = tid + 3*NT;
            skipP[pos] = 1.f / (1.f + expf(-my3));
        }
        __syncthreads();

        if (tid < NSKIP) {
            float m = -1e30f;
            #pragma unroll
            for (int j = 0; j < NSKIP; j++) m = fmaxf(m, skipP[j]);
            skipE[tid] = expf(skipP[tid] - m);
        }
        __syncthreads();
        if (tid < NSKIP) {
            float sum = 0.f;
            #pragma unroll
            for (int j = 0; j < NSKIP; j++) sum += skipE[j];
            swgt[tid] = skipE[tid] / sum;
        }
        __syncthreads();

        // weighted sum: 8 groups of 8 front-batched loads (padded, weight 0)
        float4 acc = make_float4(0.f, 0.f, 0.f, 0.f);
        #pragma unroll
        for (int g = 0; g < 64; g += 8) {
            float4 vv[8];
            #pragma unroll
            for (int j = 0; j < 8; j++)
                vv[j] = xin[((size_t)(b*TT + sidx[g+j])) * D4 + tid];
            #pragma unroll
            for (int j = 0; j < 8; j++) {
                float wgt = swgt[g+j];
                acc.x = fmaf(wgt, vv[j].x, acc.x);
                acc.y = fmaf(wgt, vv[j].y, acc.y);
                acc.z = fmaf(wgt, vv[j].z, acc.z);
                acc.w = fmaf(wgt, vv[j].w, acc.w);
            }
        }
        o4[sumBase + (unsigned)b * D4 + tid] = acc;
    } else {
        // ======== scatter block (ranks proven exact in R14 bench) ========
        __shared__ int red[6][RPB];
        __shared__ int rankS[RPB];

        int sb = (NSCAT - 1) - ((int)blockIdx.x - BB);  // reversed traversal
        int base = sb * RPB;
        int b0 = base / TT;
        int t0 = base - b0 * TT;
        bool cross = (t0 + RPB) > TT;                   // span touches batch b0+1

        // row logits (broadcast loads, L2-hot)
        float myv[RPB];
        #pragma unroll
        for (int r = 0; r < RPB; r++) myv[r] = __ldg(&g_logits[base + r]);

        // front-batched streaming x loads (MLP=8) — rank compute hides under these
        float4 v[RPB];
        #pragma unroll
        for (int r = 0; r < RPB; r++)
            v[r] = __ldcs(&xin[((size_t)(base + r)) * D4 + tid]);

        // cooperative count: 192 threads sweep the 577 logits of batch(es)
        int cnt[RPB];
        #pragma unroll
        for (int r = 0; r < RPB; r++) cnt[r] = 0;
        const float* lgA = &g_logits[b0*TT];
        const float* lgB = lgA + TT;
        for (int j = tid; j < TT; j += NT) {
            float va = __ldg(&lgA[j]);
            float vb = cross ? __ldg(&lgB[j]) : 0.f;
            #pragma unroll
            for (int r = 0; r < RPB; r++) {
                int ir = t0 + r;
                bool second = ir >= TT;
                float cv = second ? vb : va;
                int ii = second ? ir - TT : ir;
                cnt[r] += (cv > myv[r]) || (cv == myv[r] && j < ii);
            }
        }
        // reduce 192 threads -> 8 ranks
        #pragma unroll
        for (int r = 0; r < RPB; r++) {
            int c = cnt[r];
            #pragma unroll
            for (int off = 16; off; off >>= 1)
                c += __shfl_xor_sync(0xffffffffu, c, off);
            if (lane == 0) red[wrp][r] = c;
        }
        __syncthreads();
        if (tid < RPB) {
            int ssum = 0;
            #pragma unroll
            for (int wv = 0; wv < 6; wv++) ssum += red[wv][tid];
            rankS[tid] = ssum;
        }
        __syncthreads();

        // stores (v[] has arrived by now)
        #pragma unroll
        for (int r = 0; r < RPB; r++) {
            int b = b0 + ((t0 + r) >= TT);
            int rank = rankS[r];
            unsigned off4 = (rank < DENS)
                ? ((unsigned)(b*DENS + rank) * D4 + tid)
                : (skipBase + (unsigned)(b*NSKIP + ((TT-1) - rank)) * D4 + tid);
            __stcs(&o4[off4], v[r]);
        }
    }
}

extern "C" void kernel_launch(void* const* d_in, const int* in_sizes, int n_in,
                              void* d_out, int out_size) {
    const float* x    = (const float*)d_in[0];
    const float* w    = (const float*)d_in[1];
    const float* bias = (const float*)d_in[2];
    float* out = (float*)d_out;

    // 1) logits: 2 rows/warp, 8 warps/block (verified ~21us)
    logits_kernel<<<(NROWS/2 + 7) / 8, 256>>>(x, w, bias);
    // 2) scatter + summaries with cooperative block-local rank (no rank kernel)
    move_kernel<<<BB + NSCAT, NT>>>(x, out);
}